// round 1
// baseline (speedup 1.0000x reference)
#include <cuda_runtime.h>
#include <cstdint>
#include <cstddef>

// Problem shape (fixed by the reference).
#define T_MAX 8192
#define DIM   2048
#define NEXP  8

// ---------------- device-global scratch (allocation-free) ----------------
__device__ int   g_cnt[NEXP];                 // per-expert token counts
__device__ int   g_base[NEXP];                // prefix bases into ybuf rows
__device__ int   g_tok[NEXP * T_MAX];         // per-expert gathered token ids
__device__ int   g_sel[2 * T_MAX];            // per-token selected experts
__device__ int   g_pos[2 * T_MAX];            // per-token slot within expert list
__device__ float g_cw [2 * T_MAX];            // per-token softmax weights
__device__ float g_ybuf[2 * T_MAX * DIM];     // compacted per-slot GEMM results (128 MB)

// ---------------- kernel 1: zero counters ----------------
__global__ void init_kernel() {
    if (threadIdx.x < NEXP) g_cnt[threadIdx.x] = 0;
}

// ---------------- kernel 2: gating (one block per token) ----------------
__global__ __launch_bounds__(256) void gate_kernel(
    const float* __restrict__ x, const float* __restrict__ gw) {
    const int t = blockIdx.x;
    const float* xr = x + (size_t)t * DIM;
    const int base = threadIdx.x * 8;

    float xv[8];
#pragma unroll
    for (int i = 0; i < 8; i++) xv[i] = xr[base + i];

    float acc[NEXP];
#pragma unroll
    for (int e = 0; e < NEXP; e++) {
        const float* gr = gw + e * DIM + base;
        float s = 0.f;
#pragma unroll
        for (int i = 0; i < 8; i++) s = fmaf(xv[i], gr[i], s);
        acc[e] = s;
    }
#pragma unroll
    for (int e = 0; e < NEXP; e++)
#pragma unroll
        for (int off = 16; off; off >>= 1)
            acc[e] += __shfl_xor_sync(0xffffffffu, acc[e], off);

    __shared__ float red[8][NEXP];
    const int warp = threadIdx.x >> 5, lane = threadIdx.x & 31;
    if (lane == 0)
#pragma unroll
        for (int e = 0; e < NEXP; e++) red[warp][e] = acc[e];
    __syncthreads();

    if (threadIdx.x == 0) {
        float l[NEXP];
#pragma unroll
        for (int e = 0; e < NEXP; e++) {
            float s = 0.f;
#pragma unroll
            for (int w = 0; w < 8; w++) s += red[w][e];
            l[e] = s;
        }
        // top-2 with first-index tie rule (matches jax.lax.top_k)
        int e0 = 0;
#pragma unroll
        for (int e = 1; e < NEXP; e++) if (l[e] > l[e0]) e0 = e;
        int e1 = (e0 == 0) ? 1 : 0;
#pragma unroll
        for (int e = 0; e < NEXP; e++)
            if (e != e0 && e != e1 && l[e] > l[e1]) e1 = e;

        const float a1 = expf(l[e1] - l[e0]);
        const float w0 = 1.f / (1.f + a1);
        const float w1 = a1 * w0;

        const int p0 = atomicAdd(&g_cnt[e0], 1);
        g_tok[e0 * T_MAX + p0] = t;
        const int p1 = atomicAdd(&g_cnt[e1], 1);
        g_tok[e1 * T_MAX + p1] = t;

        g_sel[2 * t] = e0;  g_sel[2 * t + 1] = e1;
        g_pos[2 * t] = p0;  g_pos[2 * t + 1] = p1;
        g_cw [2 * t] = w0;  g_cw [2 * t + 1] = w1;
    }
}

// ---------------- kernel 3: 8-entry prefix scan ----------------
__global__ void scan_kernel() {
    if (threadIdx.x == 0) {
        int b = 0;
        for (int e = 0; e < NEXP; e++) { g_base[e] = b; b += g_cnt[e]; }
    }
}

// ---------------- kernel 4: grouped tf32 GEMM ----------------
#define BM 128
#define BN 128
#define BK 32
#define ASTR 36               // BK + 4 pad  -> conflict-free A frag loads
#define BSTR 136              // BN + 8 pad  -> conflict-free B frag loads
#define A_BUF (BM * ASTR)
#define B_BUF (BK * BSTR)

__device__ __forceinline__ void cp_async16(float* dst, const float* src) {
    uint32_t d = (uint32_t)__cvta_generic_to_shared(dst);
    asm volatile("cp.async.cg.shared.global [%0], [%1], 16;" :: "r"(d), "l"(src));
}
__device__ __forceinline__ uint32_t f2tf(float f) {
    uint32_t u; asm("cvt.rna.tf32.f32 %0, %1;" : "=r"(u) : "f"(f)); return u;
}

__global__ __launch_bounds__(256, 2) void moe_gemm(
    const float* __restrict__ x, const float* __restrict__ ew) {
    const int e   = blockIdx.z;
    const int cnt = g_cnt[e];
    const int m0  = blockIdx.y * BM;
    if (m0 >= cnt) return;
    const int n0  = blockIdx.x * BN;
    const int ybase = g_base[e];

    extern __shared__ float smem[];
    float* As = smem;                 // 2 stages
    float* Bs = smem + 2 * A_BUF;     // 2 stages
    __shared__ int toks[BM];

    const int tid = threadIdx.x;
    if (tid < BM) {
        const int m = m0 + tid;
        toks[tid] = (m < cnt) ? g_tok[e * T_MAX + m] : 0;
    }
    __syncthreads();

    const float* wbase = ew + (size_t)e * DIM * DIM + n0;

    auto prefetch = [&](int buf, int k0) {
        float* ab = As + buf * A_BUF;
        float* bb = Bs + buf * B_BUF;
#pragma unroll
        for (int i = 0; i < 4; i++) {               // A: 128 rows x 32 f
            const int idx = tid + i * 256;
            const int row = idx >> 3, c4 = idx & 7;
            cp_async16(ab + row * ASTR + c4 * 4,
                       x + (size_t)toks[row] * DIM + k0 + c4 * 4);
        }
#pragma unroll
        for (int i = 0; i < 4; i++) {               // B: 32 rows x 128 f
            const int idx = tid + i * 256;
            const int row = idx >> 5, c4 = idx & 31;
            cp_async16(bb + row * BSTR + c4 * 4,
                       wbase + (size_t)(k0 + row) * DIM + c4 * 4);
        }
        asm volatile("cp.async.commit_group;");
    };

    const int warpid = tid >> 5, lane = tid & 31;
    const int wm = warpid & 3, wn = warpid >> 2;    // 4x2 warp grid, 32x64 each
    const int gp = lane >> 2,  q  = lane & 3;

    float acc[2][8][4];
#pragma unroll
    for (int i = 0; i < 2; i++)
#pragma unroll
        for (int j = 0; j < 8; j++)
#pragma unroll
            for (int k = 0; k < 4; k++) acc[i][j][k] = 0.f;

    prefetch(0, 0);
    int buf = 0;
    const int KT = DIM / BK;                        // 64
    for (int kt = 0; kt < KT; kt++) {
        if (kt + 1 < KT) {
            prefetch(buf ^ 1, (kt + 1) * BK);
            asm volatile("cp.async.wait_group 1;");
        } else {
            asm volatile("cp.async.wait_group 0;");
        }
        __syncthreads();
        const float* ab = As + buf * A_BUF;
        const float* bb = Bs + buf * B_BUF;
#pragma unroll
        for (int ks = 0; ks < 4; ks++) {
            uint32_t a[2][4];
#pragma unroll
            for (int mf = 0; mf < 2; mf++) {
                const int r = wm * 32 + mf * 16 + gp;
                const float* ap = ab + r * ASTR + ks * 8;
                a[mf][0] = f2tf(ap[q]);
                a[mf][1] = f2tf(ap[8 * ASTR + q]);
                a[mf][2] = f2tf(ap[q + 4]);
                a[mf][3] = f2tf(ap[8 * ASTR + q + 4]);
            }
            uint32_t b[8][2];
#pragma unroll
            for (int nf = 0; nf < 8; nf++) {
                const int col = wn * 64 + nf * 8 + gp;
                const float* bp = bb + (ks * 8 + q) * BSTR + col;
                b[nf][0] = f2tf(bp[0]);
                b[nf][1] = f2tf(bp[4 * BSTR]);
            }
#pragma unroll
            for (int mf = 0; mf < 2; mf++)
#pragma unroll
                for (int nf = 0; nf < 8; nf++) {
                    asm volatile(
                        "mma.sync.aligned.m16n8k8.row.col.f32.tf32.tf32.f32 "
                        "{%0,%1,%2,%3}, {%4,%5,%6,%7}, {%8,%9}, {%0,%1,%2,%3};"
                        : "+f"(acc[mf][nf][0]), "+f"(acc[mf][nf][1]),
                          "+f"(acc[mf][nf][2]), "+f"(acc[mf][nf][3])
                        : "r"(a[mf][0]), "r"(a[mf][1]), "r"(a[mf][2]), "r"(a[mf][3]),
                          "r"(b[nf][0]), "r"(b[nf][1]));
                }
        }
        __syncthreads();
        buf ^= 1;
    }

    // epilogue: plain coalesced stores into compacted scratch (no atomics)
#pragma unroll
    for (int mf = 0; mf < 2; mf++) {
        const int lr0 = wm * 32 + mf * 16 + gp;
        const int lr1 = lr0 + 8;
        const bool v0 = (m0 + lr0) < cnt;
        const bool v1 = (m0 + lr1) < cnt;
        float* o0 = g_ybuf + (size_t)(ybase + m0 + lr0) * DIM + n0;
        float* o1 = g_ybuf + (size_t)(ybase + m0 + lr1) * DIM + n0;
#pragma unroll
        for (int nf = 0; nf < 8; nf++) {
            const int cb = wn * 64 + nf * 8 + 2 * q;
            if (v0) {
                float2 v = make_float2(acc[mf][nf][0], acc[mf][nf][1]);
                *(float2*)(o0 + cb) = v;
            }
            if (v1) {
                float2 v = make_float2(acc[mf][nf][2], acc[mf][nf][3]);
                *(float2*)(o1 + cb) = v;
            }
        }
    }
}

// ---------------- kernel 5: weighted combine + bias ----------------
__global__ __launch_bounds__(256) void combine_kernel(
    const float* __restrict__ eb, float* __restrict__ out) {
    const int t = blockIdx.x;
    const int e0 = g_sel[2 * t], e1 = g_sel[2 * t + 1];
    const float w0 = g_cw[2 * t], w1 = g_cw[2 * t + 1];
    const float* y0 = g_ybuf + (size_t)(g_base[e0] + g_pos[2 * t])     * DIM;
    const float* y1 = g_ybuf + (size_t)(g_base[e1] + g_pos[2 * t + 1]) * DIM;
    const float* b0 = eb + e0 * DIM;
    const float* b1 = eb + e1 * DIM;
    float* orow = out + (size_t)t * DIM;

    for (int o = threadIdx.x * 4; o < DIM; o += 256 * 4) {
        const float4 a  = *(const float4*)(y0 + o);
        const float4 b  = *(const float4*)(y1 + o);
        const float4 c0 = *(const float4*)(b0 + o);
        const float4 c1 = *(const float4*)(b1 + o);
        float4 r;
        r.x = w0 * (a.x + c0.x) + w1 * (b.x + c1.x);
        r.y = w0 * (a.y + c0.y) + w1 * (b.y + c1.y);
        r.z = w0 * (a.z + c0.z) + w1 * (b.z + c1.z);
        r.w = w0 * (a.w + c0.w) + w1 * (b.w + c1.w);
        *(float4*)(orow + o) = r;
    }
}

// ---------------- launch ----------------
extern "C" void kernel_launch(void* const* d_in, const int* in_sizes, int n_in,
                              void* d_out, int out_size) {
    const float* x  = (const float*)d_in[0];   // [T, D]
    const float* gw = (const float*)d_in[1];   // [E, D]
    const float* ew = (const float*)d_in[2];   // [E, D, D]
    const float* eb = (const float*)d_in[3];   // [E, D]
    float* out = (float*)d_out;                // [T, D]
    const int T = in_sizes[0] / DIM;

    const int smem_bytes = (2 * A_BUF + 2 * B_BUF) * (int)sizeof(float); // 71680
    cudaFuncSetAttribute(moe_gemm, cudaFuncAttributeMaxDynamicSharedMemorySize,
                         smem_bytes);

    init_kernel<<<1, 32>>>();
    gate_kernel<<<T, 256>>>(x, gw);
    scan_kernel<<<1, 1>>>();
    dim3 grid(DIM / BN, (T + BM - 1) / BM, NEXP);  // n fastest -> A reuse in L2
    moe_gemm<<<grid, 256, smem_bytes>>>(x, ew);
    combine_kernel<<<T, 256>>>(eb, out);
}

// round 3
// speedup vs baseline: 1.0018x; 1.0018x over previous
#include <cuda_runtime.h>
#include <cstdint>
#include <cstddef>

// Problem shape (fixed by the reference).
#define T_MAX 8192
#define DIM   2048
#define NEXP  8

// ---------------- device-global scratch (allocation-free) ----------------
__device__ int   g_cnt[NEXP];                 // per-expert token counts
__device__ int   g_base[NEXP];                // prefix bases into ybuf rows
__device__ int   g_tok[NEXP * T_MAX];         // per-expert gathered token ids
__device__ int   g_sel[2 * T_MAX];            // per-token selected experts
__device__ int   g_pos[2 * T_MAX];            // per-token slot within expert list
__device__ float g_cw [2 * T_MAX];            // per-token softmax weights
__device__ float g_ybuf[2 * T_MAX * DIM];     // compacted per-slot GEMM results (128 MB)

// ---------------- kernel 1: zero counters ----------------
__global__ void init_kernel() {
    if (threadIdx.x < NEXP) g_cnt[threadIdx.x] = 0;
}

// ---------------- kernel 2: gating (one block per token) ----------------
__global__ __launch_bounds__(256) void gate_kernel(
    const float* __restrict__ x, const float* __restrict__ gw) {
    const int t = blockIdx.x;
    const float* xr = x + (size_t)t * DIM;
    const int base = threadIdx.x * 8;

    float xv[8];
#pragma unroll
    for (int i = 0; i < 8; i++) xv[i] = xr[base + i];

    float acc[NEXP];
#pragma unroll
    for (int e = 0; e < NEXP; e++) {
        const float* gr = gw + e * DIM + base;
        float s = 0.f;
#pragma unroll
        for (int i = 0; i < 8; i++) s = fmaf(xv[i], gr[i], s);
        acc[e] = s;
    }
#pragma unroll
    for (int e = 0; e < NEXP; e++)
#pragma unroll
        for (int off = 16; off; off >>= 1)
            acc[e] += __shfl_xor_sync(0xffffffffu, acc[e], off);

    __shared__ float red[8][NEXP];
    const int warp = threadIdx.x >> 5, lane = threadIdx.x & 31;
    if (lane == 0)
#pragma unroll
        for (int e = 0; e < NEXP; e++) red[warp][e] = acc[e];
    __syncthreads();

    if (threadIdx.x == 0) {
        float l[NEXP];
#pragma unroll
        for (int e = 0; e < NEXP; e++) {
            float s = 0.f;
#pragma unroll
            for (int w = 0; w < 8; w++) s += red[w][e];
            l[e] = s;
        }
        // top-2 with first-index tie rule (matches jax.lax.top_k)
        int e0 = 0;
#pragma unroll
        for (int e = 1; e < NEXP; e++) if (l[e] > l[e0]) e0 = e;
        int e1 = (e0 == 0) ? 1 : 0;
#pragma unroll
        for (int e = 0; e < NEXP; e++)
            if (e != e0 && e != e1 && l[e] > l[e1]) e1 = e;

        const float a1 = expf(l[e1] - l[e0]);
        const float w0 = 1.f / (1.f + a1);
        const float w1 = a1 * w0;

        const int p0 = atomicAdd(&g_cnt[e0], 1);
        g_tok[e0 * T_MAX + p0] = t;
        const int p1 = atomicAdd(&g_cnt[e1], 1);
        g_tok[e1 * T_MAX + p1] = t;

        g_sel[2 * t] = e0;  g_sel[2 * t + 1] = e1;
        g_pos[2 * t] = p0;  g_pos[2 * t + 1] = p1;
        g_cw [2 * t] = w0;  g_cw [2 * t + 1] = w1;
    }
}

// ---------------- kernel 3: 8-entry prefix scan ----------------
__global__ void scan_kernel() {
    if (threadIdx.x == 0) {
        int b = 0;
        for (int e = 0; e < NEXP; e++) { g_base[e] = b; b += g_cnt[e]; }
    }
}

// ---------------- kernel 4: grouped tf32 GEMM ----------------
#define BM 128
#define BN 128
#define BK 32
#define ASTR 36               // BK + 4 pad  -> conflict-free A frag loads
#define BSTR 136              // BN + 8 pad  -> conflict-free B frag loads
#define A_BUF (BM * ASTR)
#define B_BUF (BK * BSTR)

__device__ __forceinline__ void cp_async16(float* dst, const float* src) {
    uint32_t d = (uint32_t)__cvta_generic_to_shared(dst);
    asm volatile("cp.async.cg.shared.global [%0], [%1], 16;" :: "r"(d), "l"(src));
}
__device__ __forceinline__ uint32_t f2tf(float f) {
    uint32_t u; asm("cvt.rna.tf32.f32 %0, %1;" : "=r"(u) : "f"(f)); return u;
}

__global__ __launch_bounds__(256, 2) void moe_gemm(
    const float* __restrict__ x, const float* __restrict__ ew) {
    const int e   = blockIdx.z;
    const int cnt = g_cnt[e];
    const int m0  = blockIdx.y * BM;
    if (m0 >= cnt) return;
    const int n0  = blockIdx.x * BN;
    const int ybase = g_base[e];

    extern __shared__ float smem[];
    float* As = smem;                 // 2 stages
    float* Bs = smem + 2 * A_BUF;     // 2 stages
    __shared__ int toks[BM];

    const int tid = threadIdx.x;
    if (tid < BM) {
        const int m = m0 + tid;
        toks[tid] = (m < cnt) ? g_tok[e * T_MAX + m] : 0;
    }
    __syncthreads();

    const float* wbase = ew + (size_t)e * DIM * DIM + n0;

    auto prefetch = [&](int buf, int k0) {
        float* ab = As + buf * A_BUF;
        float* bb = Bs + buf * B_BUF;
#pragma unroll
        for (int i = 0; i < 4; i++) {               // A: 128 rows x 32 f
            const int idx = tid + i * 256;
            const int row = idx >> 3, c4 = idx & 7;
            cp_async16(ab + row * ASTR + c4 * 4,
                       x + (size_t)toks[row] * DIM + k0 + c4 * 4);
        }
#pragma unroll
        for (int i = 0; i < 4; i++) {               // B: 32 rows x 128 f
            const int idx = tid + i * 256;
            const int row = idx >> 5, c4 = idx & 31;
            cp_async16(bb + row * BSTR + c4 * 4,
                       wbase + (size_t)(k0 + row) * DIM + c4 * 4);
        }
        asm volatile("cp.async.commit_group;");
    };

    const int warpid = tid >> 5, lane = tid & 31;
    const int wm = warpid & 3, wn = warpid >> 2;    // 4x2 warp grid, 32x64 each
    const int gp = lane >> 2,  q  = lane & 3;

    float acc[2][8][4];
#pragma unroll
    for (int i = 0; i < 2; i++)
#pragma unroll
        for (int j = 0; j < 8; j++)
#pragma unroll
            for (int k = 0; k < 4; k++) acc[i][j][k] = 0.f;

    prefetch(0, 0);
    int buf = 0;
    const int KT = DIM / BK;                        // 64
    for (int kt = 0; kt < KT; kt++) {
        if (kt + 1 < KT) {
            prefetch(buf ^ 1, (kt + 1) * BK);
            asm volatile("cp.async.wait_group 1;");
        } else {
            asm volatile("cp.async.wait_group 0;");
        }
        __syncthreads();
        const float* ab = As + buf * A_BUF;
        const float* bb = Bs + buf * B_BUF;
#pragma unroll
        for (int ks = 0; ks < 4; ks++) {
            uint32_t a[2][4];
#pragma unroll
            for (int mf = 0; mf < 2; mf++) {
                const int r = wm * 32 + mf * 16 + gp;
                const float* ap = ab + r * ASTR + ks * 8;
                a[mf][0] = f2tf(ap[q]);
                a[mf][1] = f2tf(ap[8 * ASTR + q]);
                a[mf][2] = f2tf(ap[q + 4]);
                a[mf][3] = f2tf(ap[8 * ASTR + q + 4]);
            }
            uint32_t b[8][2];
#pragma unroll
            for (int nf = 0; nf < 8; nf++) {
                const int col = wn * 64 + nf * 8 + gp;
                const float* bp = bb + (ks * 8 + q) * BSTR + col;
                b[nf][0] = f2tf(bp[0]);
                b[nf][1] = f2tf(bp[4 * BSTR]);
            }
#pragma unroll
            for (int mf = 0; mf < 2; mf++)
#pragma unroll
                for (int nf = 0; nf < 8; nf++) {
                    asm volatile(
                        "mma.sync.aligned.m16n8k8.row.col.f32.tf32.tf32.f32 "
                        "{%0,%1,%2,%3}, {%4,%5,%6,%7}, {%8,%9}, {%0,%1,%2,%3};"
                        : "+f"(acc[mf][nf][0]), "+f"(acc[mf][nf][1]),
                          "+f"(acc[mf][nf][2]), "+f"(acc[mf][nf][3])
                        : "r"(a[mf][0]), "r"(a[mf][1]), "r"(a[mf][2]), "r"(a[mf][3]),
                          "r"(b[nf][0]), "r"(b[nf][1]));
                }
        }
        __syncthreads();
        buf ^= 1;
    }

    // epilogue: plain coalesced stores into compacted scratch (no atomics)
#pragma unroll
    for (int mf = 0; mf < 2; mf++) {
        const int lr0 = wm * 32 + mf * 16 + gp;
        const int lr1 = lr0 + 8;
        const bool v0 = (m0 + lr0) < cnt;
        const bool v1 = (m0 + lr1) < cnt;
        float* o0 = g_ybuf + (size_t)(ybase + m0 + lr0) * DIM + n0;
        float* o1 = g_ybuf + (size_t)(ybase + m0 + lr1) * DIM + n0;
#pragma unroll
        for (int nf = 0; nf < 8; nf++) {
            const int cb = wn * 64 + nf * 8 + 2 * q;
            if (v0) {
                float2 v = make_float2(acc[mf][nf][0], acc[mf][nf][1]);
                *(float2*)(o0 + cb) = v;
            }
            if (v1) {
                float2 v = make_float2(acc[mf][nf][2], acc[mf][nf][3]);
                *(float2*)(o1 + cb) = v;
            }
        }
    }
}

// ---------------- kernel 5: weighted combine + bias ----------------
__global__ __launch_bounds__(256) void combine_kernel(
    const float* __restrict__ eb, float* __restrict__ out) {
    const int t = blockIdx.x;
    const int e0 = g_sel[2 * t], e1 = g_sel[2 * t + 1];
    const float w0 = g_cw[2 * t], w1 = g_cw[2 * t + 1];
    const float* y0 = g_ybuf + (size_t)(g_base[e0] + g_pos[2 * t])     * DIM;
    const float* y1 = g_ybuf + (size_t)(g_base[e1] + g_pos[2 * t + 1]) * DIM;
    const float* b0 = eb + e0 * DIM;
    const float* b1 = eb + e1 * DIM;
    float* orow = out + (size_t)t * DIM;

    for (int o = threadIdx.x * 4; o < DIM; o += 256 * 4) {
        const float4 a  = *(const float4*)(y0 + o);
        const float4 b  = *(const float4*)(y1 + o);
        const float4 c0 = *(const float4*)(b0 + o);
        const float4 c1 = *(const float4*)(b1 + o);
        float4 r;
        r.x = w0 * (a.x + c0.x) + w1 * (b.x + c1.x);
        r.y = w0 * (a.y + c0.y) + w1 * (b.y + c1.y);
        r.z = w0 * (a.z + c0.z) + w1 * (b.z + c1.z);
        r.w = w0 * (a.w + c0.w) + w1 * (b.w + c1.w);
        *(float4*)(orow + o) = r;
    }
}

// ---------------- launch ----------------
extern "C" void kernel_launch(void* const* d_in, const int* in_sizes, int n_in,
                              void* d_out, int out_size) {
    const float* x  = (const float*)d_in[0];   // [T, D]
    const float* gw = (const float*)d_in[1];   // [E, D]
    const float* ew = (const float*)d_in[2];   // [E, D, D]
    const float* eb = (const float*)d_in[3];   // [E, D]
    float* out = (float*)d_out;                // [T, D]
    const int T = in_sizes[0] / DIM;

    const int smem_bytes = (2 * A_BUF + 2 * B_BUF) * (int)sizeof(float); // 71680
    cudaFuncSetAttribute(moe_gemm, cudaFuncAttributeMaxDynamicSharedMemorySize,
                         smem_bytes);

    init_kernel<<<1, 32>>>();
    gate_kernel<<<T, 256>>>(x, gw);
    scan_kernel<<<1, 1>>>();
    dim3 grid(DIM / BN, (T + BM - 1) / BM, NEXP);  // n fastest -> A reuse in L2
    moe_gemm<<<grid, 256, smem_bytes>>>(x, ew);
    combine_kernel<<<T, 256>>>(eb, out);
}